// round 12
// baseline (speedup 1.0000x reference)
#include <cuda_runtime.h>
#include <cuda_bf16.h>
#include <cuda_fp16.h>
#include <stdint.h>

#define NB     4096
#define NROWS  8192
#define DD     128
#define BM     128
#define BN     64
#define JSPLIT 4
#define JT     (NROWS / JSPLIT / BN)   // 32
#define NBLK   ((NROWS / BM) * JSPLIT) // 256
#define LDSTR  136                      // fallback smem stride

// tcgen05 only exists in the arch-specific (sm_103a/sm_100a) compilation pass.
#if !defined(__CUDA_ARCH__) || defined(__CUDA_ARCH_FEAT_SM103_ALL) || \
    defined(__CUDA_ARCH_FEAT_SM100_ALL) || defined(__CUDA_ARCH_SPECIFIC__) || \
    defined(__CUDA_ARCH_FAMILY_SPECIFIC__)
#define HAS_TC 1
#else
#define HAS_TC 0
#endif

// z stored as f16, pre-scaled by GAM so z'.z' = Cf*sim, Cf = 10*log2(e)
#define CF_F   14.4269504088896340737f
#define GAM_F  3.798282566f              // sqrt(CF_F)

__device__ __align__(16) __half  d_zh[NROWS * DD];
__device__ float        d_S  [NROWS];
__device__ float        d_pos[NB];
__device__ unsigned int d_count;

// ------------------------------------------------------------------ utils
__device__ __forceinline__ uint32_t smem_u32(const void* p) {
    uint32_t a;
    asm("{ .reg .u64 t; cvta.to.shared.u64 t, %1; cvt.u32.u64 %0, t; }"
        : "=r"(a) : "l"(p));
    return a;
}
__device__ __forceinline__ float ex2f(float x) {
    float y; asm("ex2.approx.ftz.f32 %0, %1;" : "=f"(y) : "f"(x)); return y;
}
__device__ __forceinline__ void cpasync16(uint32_t dst, const void* src) {
    asm volatile("cp.async.cg.shared.global [%0], [%1], 16;"
                 :: "r"(dst), "l"(src) : "memory");
}
#define CP_COMMIT() asm volatile("cp.async.commit_group;" ::: "memory")
#define CP_WAIT1()  asm volatile("cp.async.wait_group 1;" ::: "memory")
#define CP_WAIT0()  asm volatile("cp.async.wait_group 0;" ::: "memory")

// ------------------------------------------------------------------ normalize + positives (+zero S/count)
__global__ void normalize_kernel(const float* __restrict__ xi,
                                 const float* __restrict__ xj) {
    int t = blockIdx.x * blockDim.x + threadIdx.x;
    if (t < NROWS) d_S[t] = 0.0f;
    if (t == 0) d_count = 0u;
    int pair = t >> 5;
    int lane = threadIdx.x & 31;
    if (pair >= NB) return;
    float4 a = ((const float4*)(xi + (size_t)pair * DD))[lane];
    float4 b = ((const float4*)(xj + (size_t)pair * DD))[lane];
    float saa = a.x*a.x + a.y*a.y + a.z*a.z + a.w*a.w;
    float sbb = b.x*b.x + b.y*b.y + b.z*b.z + b.w*b.w;
    float sab = a.x*b.x + a.y*b.y + a.z*b.z + a.w*b.w;
    #pragma unroll
    for (int o = 16; o; o >>= 1) {
        saa += __shfl_xor_sync(0xffffffffu, saa, o);
        sbb += __shfl_xor_sync(0xffffffffu, sbb, o);
        sab += __shfl_xor_sync(0xffffffffu, sab, o);
    }
    float inva = 1.0f / fmaxf(sqrtf(saa), 1e-12f);
    float invb = 1.0f / fmaxf(sqrtf(sbb), 1e-12f);
    float sa = inva * GAM_F, sb2 = invb * GAM_F;
    __half2* za = (__half2*)(d_zh + (size_t)pair * DD);
    __half2* zb = (__half2*)(d_zh + (size_t)(pair + NB) * DD);
    za[lane*2 + 0] = __floats2half2_rn(a.x*sa,  a.y*sa);
    za[lane*2 + 1] = __floats2half2_rn(a.z*sa,  a.w*sa);
    zb[lane*2 + 0] = __floats2half2_rn(b.x*sb2, b.y*sb2);
    zb[lane*2 + 1] = __floats2half2_rn(b.z*sb2, b.w*sb2);
    if (lane == 0) d_pos[pair] = sab * inva * invb;
}

// ================================================================== tcgen05 path
#if HAS_TC
#define DESC_BASE ((2ull << 61) | (1ull << 46) | (64ull << 32) | (1ull << 16))
__device__ __forceinline__ uint64_t make_desc(uint32_t addr) {
    return DESC_BASE | ((uint64_t)(addr >> 4) & 0x3FFF);
}
// idesc kind::f16: dtype=F32(1<<4), a=b=F16(0), K-major, N=64 (8<<17), M=128 (8<<24)
#define MMA_IDESC 0x8100010u

__device__ __forceinline__ void mma_f16_ss(uint32_t d, uint64_t a, uint64_t b,
                                           uint32_t en) {
    asm volatile(
        "{\n\t.reg .pred p;\n\t"
        "setp.ne.u32 p, %4, 0;\n\t"
        "tcgen05.mma.cta_group::1.kind::f16 [%0], %1, %2, %3, {%5,%5,%5,%5}, p;\n\t}"
        :: "r"(d), "l"(a), "l"(b), "r"(MMA_IDESC), "r"(en), "r"(0u) : "memory");
}

#define MBAR_INIT(a)   asm volatile("mbarrier.init.shared.b64 [%0], 1;" :: "r"(a) : "memory")
#define MBAR_INVAL(a)  asm volatile("mbarrier.inval.shared.b64 [%0];"   :: "r"(a) : "memory")
#define TC_COMMIT(a)   asm volatile("tcgen05.commit.cta_group::1.mbarrier::arrive::one.shared::cluster.b64 [%0];" :: "r"(a) : "memory")
#define TC_FENCE_AFTER()  asm volatile("tcgen05.fence::after_thread_sync;"  ::: "memory")
#define TC_FENCE_BEFORE() asm volatile("tcgen05.fence::before_thread_sync;" ::: "memory")
#define TC_WAIT_LD()      asm volatile("tcgen05.wait::ld.sync.aligned;"     ::: "memory")
#define FENCE_ASYNC()     asm volatile("fence.proxy.async.shared::cta;"     ::: "memory")

__device__ __forceinline__ void mbar_wait(uint32_t mbar, uint32_t parity) {
    uint32_t done;
    asm volatile(
        "{\n\t.reg .pred p;\n\t"
        "mbarrier.try_wait.parity.acquire.cta.shared::cta.b64 p, [%1], %2;\n\t"
        "selp.b32 %0, 1, 0, p;\n\t}"
        : "=r"(done) : "r"(mbar), "r"(parity) : "memory");
    if (!done) {
        asm volatile(
            "{\n\t.reg .pred P1;\n\t"
            "WL_%=:\n\t"
            "mbarrier.try_wait.parity.acquire.cta.shared::cta.b64 P1, [%0], %1, 0x989680;\n\t"
            "@P1 bra.uni WD_%=;\n\t"
            "bra.uni WL_%=;\n\t"
            "WD_%=:\n\t}"
            :: "r"(mbar), "r"(parity) : "memory");
    }
}

#define LDTM_X32(r, a) \
    asm volatile("tcgen05.ld.sync.aligned.32x32b.x32.b32 " \
        "{%0,%1,%2,%3,%4,%5,%6,%7,%8,%9,%10,%11,%12,%13,%14,%15," \
        "%16,%17,%18,%19,%20,%21,%22,%23,%24,%25,%26,%27,%28,%29,%30,%31}, [%32];" \
        : "=r"((r)[0]),"=r"((r)[1]),"=r"((r)[2]),"=r"((r)[3]), \
          "=r"((r)[4]),"=r"((r)[5]),"=r"((r)[6]),"=r"((r)[7]), \
          "=r"((r)[8]),"=r"((r)[9]),"=r"((r)[10]),"=r"((r)[11]), \
          "=r"((r)[12]),"=r"((r)[13]),"=r"((r)[14]),"=r"((r)[15]), \
          "=r"((r)[16]),"=r"((r)[17]),"=r"((r)[18]),"=r"((r)[19]), \
          "=r"((r)[20]),"=r"((r)[21]),"=r"((r)[22]),"=r"((r)[23]), \
          "=r"((r)[24]),"=r"((r)[25]),"=r"((r)[26]),"=r"((r)[27]), \
          "=r"((r)[28]),"=r"((r)[29]),"=r"((r)[30]),"=r"((r)[31]) \
        : "r"(a))
#endif  // HAS_TC

// blocked-atom SW128 byte offsets (rows are 256B = two 128B col-atoms)
// A tile: 128 rows, col-atom stride 16 atoms (16KB)
__device__ __forceinline__ uint32_t tile_off_a(int row, int c16) {
    uint32_t byte = (uint32_t)(((row >> 3) + ((c16 >> 3) << 4)) * 1024
                               + (row & 7) * 128 + (c16 & 7) * 16);
    return byte ^ ((byte >> 3) & 0x70);
}
// B tile: 64 rows, col-atom stride 8 atoms (8KB) -> 16KB contiguous slot
__device__ __forceinline__ uint32_t tile_off_b(int row, int c16) {
    uint32_t byte = (uint32_t)(((row >> 3) + ((c16 >> 3) << 3)) * 1024
                               + (row & 7) * 128 + (c16 & 7) * 16);
    return byte ^ ((byte >> 3) & 0x70);
}

#if !HAS_TC
__device__ __forceinline__ void mma16816(float c[4], const uint32_t a[4],
                                         const uint32_t b[2]) {
    asm volatile(
        "mma.sync.aligned.m16n8k16.row.col.f32.f16.f16.f32 "
        "{%0,%1,%2,%3}, {%4,%5,%6,%7}, {%8,%9}, {%0,%1,%2,%3};\n"
        : "+f"(c[0]), "+f"(c[1]), "+f"(c[2]), "+f"(c[3])
        : "r"(a[0]), "r"(a[1]), "r"(a[2]), "r"(a[3]), "r"(b[0]), "r"(b[1]));
}
#endif

// smem: [0] tmem ptr, [8..40) mbar[4], [1024) A 32KB, [33792) 4 x 16KB B ring
#define S_OFF_A   1024
#define S_OFF_B0  (S_OFF_A + 32768)
#define BSLOT     16384
#define SMEM_TOT  (S_OFF_B0 + 4 * BSLOT)   // 99328

__global__ void __launch_bounds__(256, 2) sim_kernel(float* __restrict__ out) {
    extern __shared__ __align__(1024) char smem[];
    const int tid   = threadIdx.x;
    const int ibase = blockIdx.x * BM;
    const int j0    = blockIdx.y * (NROWS / JSPLIT);

#if HAS_TC
    const uint32_t sb = smem_u32(smem);
    const int w    = tid >> 5, lane = tid & 31;
    const int sp   = w & 3, half = w >> 2;
    const int rg   = ibase + sp * 32 + lane;
    const int crow = tid >> 4, cc16 = tid & 15;   // B-slot copy coords (64x16)
    uint32_t z16;
    { __half2 z2 = __float2half2_rn(0.f); z16 = *(uint32_t*)&z2; }

    // prologue loads: A + B0 (group0), B1 (group1)
    #pragma unroll
    for (int u = 0; u < 8; u++) {
        int c = tid + u * 256;
        int row = c >> 4, c16 = c & 15;
        cpasync16(sb + S_OFF_A + tile_off_a(row, c16),
                  d_zh + (size_t)(ibase + row) * DD + c16 * 8);
    }
    {
        uint32_t so = tile_off_b(crow, cc16);
        #pragma unroll
        for (int u = 0; u < 4; u++)
            cpasync16(sb + S_OFF_B0 + so + ((u * 16) << 8) * 0 +
                      tile_off_b(crow + u * 16, cc16) - tile_off_b(crow, cc16) + 0,
                      d_zh + (size_t)(j0 + crow + u * 16) * DD + cc16 * 8);
    }
    CP_COMMIT();
    #pragma unroll
    for (int u = 0; u < 4; u++)
        cpasync16(sb + S_OFF_B0 + BSLOT + tile_off_b(crow + u * 16, cc16),
                  d_zh + (size_t)(j0 + BN + crow + u * 16) * DD + cc16 * 8);
    CP_COMMIT();

    if (w == 0)
        asm volatile("tcgen05.alloc.cta_group::1.sync.aligned.shared::cta.b32 [%0], 256;"
                     :: "r"(sb) : "memory");
    if (tid == 0) {
        MBAR_INIT(sb + 8); MBAR_INIT(sb + 16);
        MBAR_INIT(sb + 24); MBAR_INIT(sb + 32);
    }
    __syncthreads();
    uint32_t tmem;
    asm volatile("ld.shared.b32 %0, [%1];" : "=r"(tmem) : "r"(sb));
    const uint64_t a_desc = make_desc(sb + S_OFF_A);

    float rowsum = 0.0f;

    for (int t = 0; t < JT + 2; ++t) {
        if (t < JT) {
            if (t < JT - 1) { CP_WAIT1(); } else { CP_WAIT0(); }
            FENCE_ASYNC();
            __syncthreads();
            if (tid == 0) {
                const uint64_t b_desc = make_desc(sb + S_OFF_B0 + (t & 3) * BSLOT);
                const uint32_t dtm = tmem + (t & 3) * 64;
                #pragma unroll
                for (int k = 0; k < 8; k++) {
                    uint32_t ao = (k < 4) ? 2u * k : 1024u + 2u * (k - 4);
                    uint32_t bo = (k < 4) ? 2u * k : 512u  + 2u * (k - 4);
                    mma_f16_ss(dtm, a_desc + ao, b_desc + bo, k > 0);
                }
                TC_COMMIT(sb + 8 + (t & 3) * 8);
            }
        }

        uint32_t r[32];
        const int e = t - 2;
        if (e >= 0) {
            mbar_wait(sb + 8 + (e & 3) * 8, (e >> 2) & 1);
            TC_FENCE_AFTER();
            LDTM_X32(r, tmem + (e & 3) * 64 + ((uint32_t)sp << 21) + half * 32);
        }

        // prefetch B(t+2) into freed slot (covers LDTM latency)
        const int f = t + 2;
        if (f < JT) {
            const int jb = j0 + f * BN;
            #pragma unroll
            for (int u = 0; u < 4; u++)
                cpasync16(sb + S_OFF_B0 + (f & 3) * BSLOT +
                          tile_off_b(crow + u * 16, cc16),
                          d_zh + (size_t)(jb + crow + u * 16) * DD + cc16 * 8);
            CP_COMMIT();
        }

        if (e >= 0) {
            TC_WAIT_LD();
            const int jb1 = j0 + e * BN;
            const bool isdiag = (jb1 - ibase) == ((sp >> 1) << 6);
            if (!isdiag) {
                uint32_t a0 = z16, a1 = z16, a2 = z16, a3 = z16;
                #pragma unroll
                for (int j = 0; j < 32; j += 8) {
                    uint32_t h0, h1, h2, h3, e0, e1, e2, e3;
                    asm("cvt.rn.f16x2.f32 %0, %1, %2;" : "=r"(h0)
                        : "f"(__uint_as_float(r[j+1])), "f"(__uint_as_float(r[j+0])));
                    asm("cvt.rn.f16x2.f32 %0, %1, %2;" : "=r"(h1)
                        : "f"(__uint_as_float(r[j+3])), "f"(__uint_as_float(r[j+2])));
                    asm("cvt.rn.f16x2.f32 %0, %1, %2;" : "=r"(h2)
                        : "f"(__uint_as_float(r[j+5])), "f"(__uint_as_float(r[j+4])));
                    asm("cvt.rn.f16x2.f32 %0, %1, %2;" : "=r"(h3)
                        : "f"(__uint_as_float(r[j+7])), "f"(__uint_as_float(r[j+6])));
                    asm("ex2.approx.f16x2 %0, %1;" : "=r"(e0) : "r"(h0));
                    asm("ex2.approx.f16x2 %0, %1;" : "=r"(e1) : "r"(h1));
                    asm("ex2.approx.f16x2 %0, %1;" : "=r"(e2) : "r"(h2));
                    asm("ex2.approx.f16x2 %0, %1;" : "=r"(e3) : "r"(h3));
                    asm("add.f16x2 %0, %1, %2;" : "=r"(a0) : "r"(a0), "r"(e0));
                    asm("add.f16x2 %0, %1, %2;" : "=r"(a1) : "r"(a1), "r"(e1));
                    asm("add.f16x2 %0, %1, %2;" : "=r"(a2) : "r"(a2), "r"(e2));
                    asm("add.f16x2 %0, %1, %2;" : "=r"(a3) : "r"(a3), "r"(e3));
                }
                float2 f0 = __half22float2(*(__half2*)&a0);
                float2 f1 = __half22float2(*(__half2*)&a1);
                float2 f2 = __half22float2(*(__half2*)&a2);
                float2 f3 = __half22float2(*(__half2*)&a3);
                rowsum += ((f0.x + f0.y) + (f1.x + f1.y))
                        + ((f2.x + f2.y) + (f3.x + f3.y));
            } else {
                // diag j-tile for this warp: exact f32 masking
                // dcol = rg - jb1 - 32*half == lane iff half == (sp&1)
                const int dcol = (half == (sp & 1)) ? lane : -1;
                float s0 = 0.f, s1 = 0.f;
                #pragma unroll
                for (int j = 0; j < 32; j += 2) {
                    float e0 = ex2f(__uint_as_float(r[j]));
                    float e1 = ex2f(__uint_as_float(r[j + 1]));
                    if (j != dcol)     s0 += e0;
                    if (j + 1 != dcol) s1 += e1;
                }
                rowsum += s0 + s1;
            }
            TC_FENCE_BEFORE();
        }
    }

    atomicAdd(&d_S[rg], rowsum);

    __syncthreads();
    if (tid == 0) {
        MBAR_INVAL(sb + 8);  MBAR_INVAL(sb + 16);
        MBAR_INVAL(sb + 24); MBAR_INVAL(sb + 32);
    }
    __syncthreads();
    if (w == 0) {
        asm volatile("tcgen05.relinquish_alloc_permit.cta_group::1.sync.aligned;");
        asm volatile("tcgen05.dealloc.cta_group::1.sync.aligned.b32 %0, 256;"
                     :: "r"(tmem));
    }
#else
    // ---------------- HMMA fallback (plain sm_103 pass; never runs on GB300) ------
    __half* As = (__half*)smem;
    __half* Bs = As + BM * LDSTR;

    const int wid    = tid >> 5;
    const int lane   = tid & 31;
    const int g      = lane >> 2;
    const int q      = lane & 3;
    const int warp_m = wid & 3;
    const int warp_n = wid >> 2;

    for (int c = tid; c < BM * DD / 8; c += 256) {
        int row = c >> 4, c8 = c & 15;
        *(uint4*)(As + row * LDSTR + c8 * 8) =
            *(const uint4*)(d_zh + (size_t)(ibase + row) * DD + c8 * 8);
    }

    float rowsum[2][2] = {{0.f, 0.f}, {0.f, 0.f}};

    for (int jt = 0; jt < 16; ++jt) {
        const int jbase = j0 + jt * 128;
        __syncthreads();
        for (int c = tid; c < 128 * DD / 8; c += 256) {
            int row = c >> 4, c8 = c & 15;
            *(uint4*)(Bs + row * LDSTR + c8 * 8) =
                *(const uint4*)(d_zh + (size_t)(jbase + row) * DD + c8 * 8);
        }
        __syncthreads();

        float acc[2][8][4];
        #pragma unroll
        for (int mf = 0; mf < 2; mf++)
            #pragma unroll
            for (int nf = 0; nf < 8; nf++)
                #pragma unroll
                for (int e = 0; e < 4; e++) acc[mf][nf][e] = 0.f;

        #pragma unroll
        for (int kk = 0; kk < 8; kk++) {
            const int kb = kk * 16;
            uint32_t a[2][4], b[8][2];
            #pragma unroll
            for (int mf = 0; mf < 2; mf++) {
                const __half* pp =
                    As + (warp_m * 32 + mf * 16 + g) * LDSTR + kb + 2 * q;
                a[mf][0] = *(const uint32_t*)pp;
                a[mf][1] = *(const uint32_t*)(pp + 8 * LDSTR);
                a[mf][2] = *(const uint32_t*)(pp + 8);
                a[mf][3] = *(const uint32_t*)(pp + 8 * LDSTR + 8);
            }
            #pragma unroll
            for (int nf = 0; nf < 8; nf++) {
                const __half* pp =
                    Bs + (warp_n * 64 + nf * 8 + g) * LDSTR + kb + 2 * q;
                b[nf][0] = *(const uint32_t*)pp;
                b[nf][1] = *(const uint32_t*)(pp + 8);
            }
            #pragma unroll
            for (int mf = 0; mf < 2; mf++)
                #pragma unroll
                for (int nf = 0; nf < 8; nf++)
                    mma16816(acc[mf][nf], a[mf], b[nf]);
        }

        #pragma unroll
        for (int mf = 0; mf < 2; mf++)
            #pragma unroll
            for (int nf = 0; nf < 8; nf++)
                #pragma unroll
                for (int e = 0; e < 4; e++) {
                    int rgl = ibase + warp_m * 32 + mf * 16 + g + ((e >> 1) << 3);
                    int cg  = jbase + warp_n * 64 + nf * 8 + q * 2 + (e & 1);
                    float ev = (rgl == cg) ? 0.f : exp2f(acc[mf][nf][e]);
                    rowsum[mf][e >> 1] += ev;
                }
    }

    #pragma unroll
    for (int mf = 0; mf < 2; mf++)
        #pragma unroll
        for (int h = 0; h < 2; h++) {
            float s = rowsum[mf][h];
            s += __shfl_xor_sync(0xffffffffu, s, 1);
            s += __shfl_xor_sync(0xffffffffu, s, 2);
            if (q == 0)
                atomicAdd(&d_S[ibase + warp_m * 32 + mf * 16 + g + h * 8], s);
        }
#endif

    // -------- last-block final reduction --------
    __shared__ double red[8];
    __shared__ int lastflag;
    __threadfence();
    __syncthreads();
    if (tid == 0) {
        unsigned v = atomicAdd(&d_count, 1u);
        lastflag = (v == NBLK - 1);
    }
    __syncthreads();
    if (lastflag) {
        __threadfence();
        double s = 0.0;
        for (int i = tid; i < NROWS; i += 256) s += (double)__logf(d_S[i]);
        for (int i = tid; i < NB;    i += 256) s -= 20.0 * (double)d_pos[i];
        #pragma unroll
        for (int o = 16; o; o >>= 1) s += __shfl_xor_sync(0xffffffffu, s, o);
        if ((tid & 31) == 0) red[tid >> 5] = s;
        __syncthreads();
        if (tid == 0) {
            double t2 = 0.0;
            #pragma unroll
            for (int u = 0; u < 8; u++) t2 += red[u];
            out[0] = (float)(t2 / (double)NROWS);
        }
    }
}

// ------------------------------------------------------------------ launch
extern "C" void kernel_launch(void* const* d_in, const int* in_sizes, int n_in,
                              void* d_out, int out_size) {
    const float* xi = (const float*)d_in[0];
    const float* xj = (const float*)d_in[1];
    float* out = (float*)d_out;

    cudaFuncSetAttribute(sim_kernel,
                         cudaFuncAttributeMaxDynamicSharedMemorySize, SMEM_TOT);

    normalize_kernel<<<NB / 8, 256>>>(xi, xj);
    dim3 grid(NROWS / BM, JSPLIT);
    sim_kernel<<<grid, 256, SMEM_TOT>>>(out);
}

// round 15
// speedup vs baseline: 1.1903x; 1.1903x over previous
#include <cuda_runtime.h>
#include <cuda_bf16.h>
#include <cuda_fp16.h>
#include <stdint.h>

#define NB     4096
#define NROWS  8192
#define DD     128
#define BM     128
#define BN     128
#define JSPLIT 4
#define JT     (NROWS / JSPLIT / BN)   // 16
#define NBLK   ((NROWS / BM) * JSPLIT) // 256
#define LDSTR  136                      // fallback smem stride

// tcgen05 only exists in the arch-specific (sm_103a/sm_100a) compilation pass.
#if !defined(__CUDA_ARCH__) || defined(__CUDA_ARCH_FEAT_SM103_ALL) || \
    defined(__CUDA_ARCH_FEAT_SM100_ALL) || defined(__CUDA_ARCH_SPECIFIC__) || \
    defined(__CUDA_ARCH_FAMILY_SPECIFIC__)
#define HAS_TC 1
#else
#define HAS_TC 0
#endif

// z stored as f16, pre-scaled by GAM so z'.z' = Cf*sim, Cf = 10*log2(e)
#define CF_F   14.4269504088896340737f
#define GAM_F  3.798282566f              // sqrt(CF_F)

__device__ __align__(16) __half  d_zh[NROWS * DD];
__device__ float        d_S  [NROWS];
__device__ float        d_pos[NB];
__device__ unsigned int d_count;

// ------------------------------------------------------------------ utils
__device__ __forceinline__ uint32_t smem_u32(const void* p) {
    uint32_t a;
    asm("{ .reg .u64 t; cvta.to.shared.u64 t, %1; cvt.u32.u64 %0, t; }"
        : "=r"(a) : "l"(p));
    return a;
}
__device__ __forceinline__ float ex2f(float x) {
    float y; asm("ex2.approx.ftz.f32 %0, %1;" : "=f"(y) : "f"(x)); return y;
}
__device__ __forceinline__ void cpasync16(uint32_t dst, const void* src) {
    asm volatile("cp.async.cg.shared.global [%0], [%1], 16;"
                 :: "r"(dst), "l"(src) : "memory");
}
#define CPA_ARRIVE(a) \
    asm volatile("cp.async.mbarrier.arrive.noinc.shared.b64 [%0];" \
                 :: "r"(a) : "memory")

// ------------------------------------------------------------------ normalize + positives (+zero S/count)
__global__ void normalize_kernel(const float* __restrict__ xi,
                                 const float* __restrict__ xj) {
    int t = blockIdx.x * blockDim.x + threadIdx.x;
    if (t < NROWS) d_S[t] = 0.0f;
    if (t == 0) d_count = 0u;
    int pair = t >> 5;
    int lane = threadIdx.x & 31;
    if (pair >= NB) return;
    float4 a = ((const float4*)(xi + (size_t)pair * DD))[lane];
    float4 b = ((const float4*)(xj + (size_t)pair * DD))[lane];
    float saa = a.x*a.x + a.y*a.y + a.z*a.z + a.w*a.w;
    float sbb = b.x*b.x + b.y*b.y + b.z*b.z + b.w*b.w;
    float sab = a.x*b.x + a.y*b.y + a.z*b.z + a.w*b.w;
    #pragma unroll
    for (int o = 16; o; o >>= 1) {
        saa += __shfl_xor_sync(0xffffffffu, saa, o);
        sbb += __shfl_xor_sync(0xffffffffu, sbb, o);
        sab += __shfl_xor_sync(0xffffffffu, sab, o);
    }
    float inva = 1.0f / fmaxf(sqrtf(saa), 1e-12f);
    float invb = 1.0f / fmaxf(sqrtf(sbb), 1e-12f);
    float sa = inva * GAM_F, sb2 = invb * GAM_F;
    __half2* za = (__half2*)(d_zh + (size_t)pair * DD);
    __half2* zb = (__half2*)(d_zh + (size_t)(pair + NB) * DD);
    za[lane*2 + 0] = __floats2half2_rn(a.x*sa,  a.y*sa);
    za[lane*2 + 1] = __floats2half2_rn(a.z*sa,  a.w*sa);
    zb[lane*2 + 0] = __floats2half2_rn(b.x*sb2, b.y*sb2);
    zb[lane*2 + 1] = __floats2half2_rn(b.z*sb2, b.w*sb2);
    if (lane == 0) d_pos[pair] = sab * inva * invb;
}

// ================================================================== tcgen05 path
#if HAS_TC
#define DESC_BASE ((2ull << 61) | (1ull << 46) | (64ull << 32) | (1ull << 16))
__device__ __forceinline__ uint64_t make_desc(uint32_t addr) {
    return DESC_BASE | ((uint64_t)(addr >> 4) & 0x3FFF);
}
// idesc kind::f16: dtype=F32(1<<4), a=b=F16(0) K-major, N=128 (16<<17), M=128 (8<<24)
#define MMA_IDESC 0x8200010u

__device__ __forceinline__ void mma_f16_ss(uint32_t d, uint64_t a, uint64_t b,
                                           uint32_t en) {
    asm volatile(
        "{\n\t.reg .pred p;\n\t"
        "setp.ne.u32 p, %4, 0;\n\t"
        "tcgen05.mma.cta_group::1.kind::f16 [%0], %1, %2, %3, {%5,%5,%5,%5}, p;\n\t}"
        :: "r"(d), "l"(a), "l"(b), "r"(MMA_IDESC), "r"(en), "r"(0u) : "memory");
}

#define MBAR_INIT(a, n)  asm volatile("mbarrier.init.shared.b64 [%0], %1;" :: "r"(a), "r"(n) : "memory")
#define MBAR_INVAL(a)    asm volatile("mbarrier.inval.shared.b64 [%0];"    :: "r"(a) : "memory")
#define MBAR_ARRIVE(a)   asm volatile("mbarrier.arrive.shared.b64 _, [%0];" :: "r"(a) : "memory")
#define TC_COMMIT(a)   asm volatile("tcgen05.commit.cta_group::1.mbarrier::arrive::one.shared::cluster.b64 [%0];" :: "r"(a) : "memory")
#define TC_FENCE_AFTER()  asm volatile("tcgen05.fence::after_thread_sync;"  ::: "memory")
#define TC_FENCE_BEFORE() asm volatile("tcgen05.fence::before_thread_sync;" ::: "memory")
#define TC_WAIT_LD()      asm volatile("tcgen05.wait::ld.sync.aligned;"     ::: "memory")
#define FENCE_ASYNC()     asm volatile("fence.proxy.async.shared::cta;"     ::: "memory")

__device__ __forceinline__ void mbar_wait(uint32_t mbar, uint32_t parity) {
    uint32_t done;
    asm volatile(
        "{\n\t.reg .pred p;\n\t"
        "mbarrier.try_wait.parity.acquire.cta.shared::cta.b64 p, [%1], %2;\n\t"
        "selp.b32 %0, 1, 0, p;\n\t}"
        : "=r"(done) : "r"(mbar), "r"(parity) : "memory");
    if (!done) {
        asm volatile(
            "{\n\t.reg .pred P1;\n\t"
            "WL_%=:\n\t"
            "mbarrier.try_wait.parity.acquire.cta.shared::cta.b64 P1, [%0], %1, 0x989680;\n\t"
            "@P1 bra.uni WD_%=;\n\t"
            "bra.uni WL_%=;\n\t"
            "WD_%=:\n\t}"
            :: "r"(mbar), "r"(parity) : "memory");
    }
}

#define LDTM_X32(r, a) \
    asm volatile("tcgen05.ld.sync.aligned.32x32b.x32.b32 " \
        "{%0,%1,%2,%3,%4,%5,%6,%7,%8,%9,%10,%11,%12,%13,%14,%15," \
        "%16,%17,%18,%19,%20,%21,%22,%23,%24,%25,%26,%27,%28,%29,%30,%31}, [%32];" \
        : "=r"((r)[0]),"=r"((r)[1]),"=r"((r)[2]),"=r"((r)[3]), \
          "=r"((r)[4]),"=r"((r)[5]),"=r"((r)[6]),"=r"((r)[7]), \
          "=r"((r)[8]),"=r"((r)[9]),"=r"((r)[10]),"=r"((r)[11]), \
          "=r"((r)[12]),"=r"((r)[13]),"=r"((r)[14]),"=r"((r)[15]), \
          "=r"((r)[16]),"=r"((r)[17]),"=r"((r)[18]),"=r"((r)[19]), \
          "=r"((r)[20]),"=r"((r)[21]),"=r"((r)[22]),"=r"((r)[23]), \
          "=r"((r)[24]),"=r"((r)[25]),"=r"((r)[26]),"=r"((r)[27]), \
          "=r"((r)[28]),"=r"((r)[29]),"=r"((r)[30]),"=r"((r)[31]) \
        : "r"(a))
#endif  // HAS_TC

// blocked-atom SW128 byte offset for (row, 16B-chunk) of a 128x128 f16 tile
__device__ __forceinline__ uint32_t tile_off(int row, int c16) {
    uint32_t byte = (uint32_t)(((row >> 3) + ((c16 >> 3) << 4)) * 1024
                               + (row & 7) * 128 + (c16 & 7) * 16);
    return byte ^ ((byte >> 3) & 0x70);
}

#if !HAS_TC
__device__ __forceinline__ void mma16816(float c[4], const uint32_t a[4],
                                         const uint32_t b[2]) {
    asm volatile(
        "mma.sync.aligned.m16n8k16.row.col.f32.f16.f16.f32 "
        "{%0,%1,%2,%3}, {%4,%5,%6,%7}, {%8,%9}, {%0,%1,%2,%3};\n"
        : "+f"(c[0]), "+f"(c[1]), "+f"(c[2]), "+f"(c[3])
        : "r"(a[0]), "r"(a[1]), "r"(a[2]), "r"(a[3]), "r"(b[0]), "r"(b[1]));
}
#endif

// smem: [0] tmem ptr, [8..24) mma_done[2], [24..40) epi_done[2],
//       [40..56) b_full[2], [1024) A 32KB, [+32K) B0, B1
#define S_OFF_A   1024
#define S_OFF_B0  (S_OFF_A + 32768)
#define SMEM_TOT  (S_OFF_B0 + 2 * 32768)

__global__ void __launch_bounds__(256, 2) sim_kernel(float* __restrict__ out) {
    extern __shared__ __align__(1024) char smem[];
    const int tid   = threadIdx.x;
    const int ibase = blockIdx.x * BM;
    const int j0    = blockIdx.y * (NROWS / JSPLIT);

#if HAS_TC
    const uint32_t sb = smem_u32(smem);
    const int w    = tid >> 5, lane = tid & 31;
    const int sp   = w & 3, half = w >> 2;
    const int rg   = ibase + sp * 32 + lane;
    uint32_t z16;
    { __half2 z2 = __float2half2_rn(0.f); z16 = *(uint32_t*)&z2; }

    const uint32_t mb_mma = sb + 8;    // +s*8, count 1
    const uint32_t mb_epi = sb + 24;   // +s*8, count 8
    const uint32_t mb_bf  = sb + 40;   // +s*8, count 256

    if (tid == 0) {
        MBAR_INIT(mb_mma + 0, 1);   MBAR_INIT(mb_mma + 8, 1);
        MBAR_INIT(mb_epi + 0, 8);   MBAR_INIT(mb_epi + 8, 8);
        MBAR_INIT(mb_bf  + 0, 256); MBAR_INIT(mb_bf  + 8, 256);
    }
    if (w == 0)
        asm volatile("tcgen05.alloc.cta_group::1.sync.aligned.shared::cta.b32 [%0], 256;"
                     :: "r"(sb) : "memory");
    __syncthreads();
    uint32_t tmem;
    asm volatile("ld.shared.b32 %0, [%1];" : "=r"(tmem) : "r"(sb));

    // prologue: A + B0, arrive b_full[0]; B1, arrive b_full[1]
    #pragma unroll
    for (int u = 0; u < 8; u++) {
        int c = tid + u * 256;
        int row = c >> 4, c16 = c & 15;
        uint32_t so = tile_off(row, c16);
        cpasync16(sb + S_OFF_A  + so, d_zh + (size_t)(ibase + row) * DD + c16 * 8);
        cpasync16(sb + S_OFF_B0 + so, d_zh + (size_t)(j0    + row) * DD + c16 * 8);
    }
    CPA_ARRIVE(mb_bf + 0);
    #pragma unroll
    for (int u = 0; u < 8; u++) {
        int c = tid + u * 256;
        int row = c >> 4, c16 = c & 15;
        cpasync16(sb + S_OFF_B0 + 32768 + tile_off(row, c16),
                  d_zh + (size_t)(j0 + BN + row) * DD + c16 * 8);
    }
    CPA_ARRIVE(mb_bf + 8);

    const uint64_t a_desc = make_desc(sb + S_OFF_A);

    // MMA(0)
    if (tid == 0) {
        mbar_wait(mb_bf + 0, 0);
        FENCE_ASYNC();
        const uint64_t b_desc = make_desc(sb + S_OFF_B0);
        #pragma unroll
        for (int k = 0; k < 8; k++) {
            uint32_t off = (k < 4) ? 2u * k : 1024u + 2u * (k - 4);
            mma_f16_ss(tmem, a_desc + off, b_desc + off, k > 0);
        }
        TC_COMMIT(mb_mma + 0);
    }

    float rowsum = 0.0f;

    for (int jt = 1; jt <= JT; ++jt) {
        const int p = jt & 1;

        // tid0: issue MMA(jt) once B(jt) loaded and D[p]'s old readers done
        if (tid == 0 && jt < JT) {
            mbar_wait(mb_bf + p * 8, (jt >> 1) & 1);
            if (jt >= 2) mbar_wait(mb_epi + p * 8, ((jt - 2) >> 1) & 1);
            FENCE_ASYNC();
            TC_FENCE_AFTER();
            const uint64_t b_desc = make_desc(sb + S_OFF_B0 + p * 32768);
            const uint32_t dtm = tmem + p * 128;
            #pragma unroll
            for (int k = 0; k < 8; k++) {
                uint32_t off = (k < 4) ? 2u * k : 1024u + 2u * (k - 4);
                mma_f16_ss(dtm, a_desc + off, b_desc + off, k > 0);
            }
            TC_COMMIT(mb_mma + p * 8);
        }

        // per-warp: epilogue of tile e = jt-1 from D[e&1]
        const int e  = jt - 1;
        const int s  = e & 1;
        mbar_wait(mb_mma + s * 8, (e >> 1) & 1);
        TC_FENCE_AFTER();
        const uint32_t taddr = tmem + s * 128 + ((uint32_t)sp << 21) + half * 64;
        uint32_t r0[32], r1[32];
        LDTM_X32(r0, taddr);
        LDTM_X32(r1, taddr + 32);

        // prefetch B(jt+1) into slot (jt+1)&1 (freed: MMA(jt-1) done reading it)
        if (jt + 1 < JT) {
            const int jb = j0 + (jt + 1) * BN;
            const uint32_t bdst = sb + S_OFF_B0 + ((jt + 1) & 1) * 32768;
            #pragma unroll
            for (int u = 0; u < 8; u++) {
                int c = tid + u * 256;
                int row = c >> 4, c16 = c & 15;
                cpasync16(bdst + tile_off(row, c16),
                          d_zh + (size_t)(jb + row) * DD + c16 * 8);
            }
            CPA_ARRIVE(mb_bf + ((jt + 1) & 1) * 8);
        }

        TC_WAIT_LD();
        TC_FENCE_BEFORE();
        if (lane == 0) MBAR_ARRIVE(mb_epi + s * 8);   // D slot s free

        const int jb1 = j0 + e * BN;
        if (jb1 != ibase) {
            uint32_t a0 = z16, a1 = z16, a2 = z16, a3 = z16;
            #pragma unroll
            for (int j = 0; j < 32; j += 4) {
                uint32_t h0, h1, e0, e1;
                asm("cvt.rn.f16x2.f32 %0, %1, %2;" : "=r"(h0)
                    : "f"(__uint_as_float(r0[j + 1])), "f"(__uint_as_float(r0[j])));
                asm("cvt.rn.f16x2.f32 %0, %1, %2;" : "=r"(h1)
                    : "f"(__uint_as_float(r0[j + 3])), "f"(__uint_as_float(r0[j + 2])));
                asm("ex2.approx.f16x2 %0, %1;" : "=r"(e0) : "r"(h0));
                asm("ex2.approx.f16x2 %0, %1;" : "=r"(e1) : "r"(h1));
                asm("add.f16x2 %0, %1, %2;" : "=r"(a0) : "r"(a0), "r"(e0));
                asm("add.f16x2 %0, %1, %2;" : "=r"(a1) : "r"(a1), "r"(e1));
                asm("cvt.rn.f16x2.f32 %0, %1, %2;" : "=r"(h0)
                    : "f"(__uint_as_float(r1[j + 1])), "f"(__uint_as_float(r1[j])));
                asm("cvt.rn.f16x2.f32 %0, %1, %2;" : "=r"(h1)
                    : "f"(__uint_as_float(r1[j + 3])), "f"(__uint_as_float(r1[j + 2])));
                asm("ex2.approx.f16x2 %0, %1;" : "=r"(e0) : "r"(h0));
                asm("ex2.approx.f16x2 %0, %1;" : "=r"(e1) : "r"(h1));
                asm("add.f16x2 %0, %1, %2;" : "=r"(a2) : "r"(a2), "r"(e0));
                asm("add.f16x2 %0, %1, %2;" : "=r"(a3) : "r"(a3), "r"(e1));
            }
            float2 f0 = __half22float2(*(__half2*)&a0);
            float2 f1 = __half22float2(*(__half2*)&a1);
            float2 f2 = __half22float2(*(__half2*)&a2);
            float2 f3 = __half22float2(*(__half2*)&a3);
            rowsum += ((f0.x + f0.y) + (f1.x + f1.y))
                    + ((f2.x + f2.y) + (f3.x + f3.y));
        } else {
            // diagonal tile: exact f32 path with masking (D = Cf*sim already)
            const int dcol = rg - jb1 - half * 64;
            float s0 = 0.f, s1 = 0.f;
            #pragma unroll
            for (int j = 0; j < 32; j++) {
                float ev = ex2f(__uint_as_float(r0[j]));
                if (j != dcol) s0 += ev;
            }
            #pragma unroll
            for (int j = 0; j < 32; j++) {
                float ev = ex2f(__uint_as_float(r1[j]));
                if (j + 32 != dcol) s1 += ev;
            }
            rowsum += s0 + s1;
        }
    }

    atomicAdd(&d_S[rg], rowsum);

    __syncthreads();
    if (tid == 0) {
        MBAR_INVAL(mb_mma + 0); MBAR_INVAL(mb_mma + 8);
        MBAR_INVAL(mb_epi + 0); MBAR_INVAL(mb_epi + 8);
        MBAR_INVAL(mb_bf  + 0); MBAR_INVAL(mb_bf  + 8);
    }
    __syncthreads();
    if (w == 0) {
        asm volatile("tcgen05.relinquish_alloc_permit.cta_group::1.sync.aligned;");
        asm volatile("tcgen05.dealloc.cta_group::1.sync.aligned.b32 %0, 256;"
                     :: "r"(tmem));
    }
#else
    // ---------------- HMMA fallback (plain sm_103 pass; never runs on GB300) ------
    __half* As = (__half*)smem;
    __half* Bs = As + BM * LDSTR;

    const int wid    = tid >> 5;
    const int lane   = tid & 31;
    const int g      = lane >> 2;
    const int q      = lane & 3;
    const int warp_m = wid & 3;
    const int warp_n = wid >> 2;

    for (int c = tid; c < BM * DD / 8; c += 256) {
        int row = c >> 4, c8 = c & 15;
        *(uint4*)(As + row * LDSTR + c8 * 8) =
            *(const uint4*)(d_zh + (size_t)(ibase + row) * DD + c8 * 8);
    }

    float rowsum[2][2] = {{0.f, 0.f}, {0.f, 0.f}};

    for (int jt = 0; jt < JT; ++jt) {
        const int jbase = j0 + jt * BN;
        __syncthreads();
        for (int c = tid; c < BN * DD / 8; c += 256) {
            int row = c >> 4, c8 = c & 15;
            *(uint4*)(Bs + row * LDSTR + c8 * 8) =
                *(const uint4*)(d_zh + (size_t)(jbase + row) * DD + c8 * 8);
        }
        __syncthreads();

        float acc[2][8][4];
        #pragma unroll
        for (int mf = 0; mf < 2; mf++)
            #pragma unroll
            for (int nf = 0; nf < 8; nf++)
                #pragma unroll
                for (int e2 = 0; e2 < 4; e2++) acc[mf][nf][e2] = 0.f;

        #pragma unroll
        for (int kk = 0; kk < 8; kk++) {
            const int kb = kk * 16;
            uint32_t a[2][4], b[8][2];
            #pragma unroll
            for (int mf = 0; mf < 2; mf++) {
                const __half* pp =
                    As + (warp_m * 32 + mf * 16 + g) * LDSTR + kb + 2 * q;
                a[mf][0] = *(const uint32_t*)pp;
                a[mf][1] = *(const uint32_t*)(pp + 8 * LDSTR);
                a[mf][2] = *(const uint32_t*)(pp + 8);
                a[mf][3] = *(const uint32_t*)(pp + 8 * LDSTR + 8);
            }
            #pragma unroll
            for (int nf = 0; nf < 8; nf++) {
                const __half* pp =
                    Bs + (warp_n * 64 + nf * 8 + g) * LDSTR + kb + 2 * q;
                b[nf][0] = *(const uint32_t*)pp;
                b[nf][1] = *(const uint32_t*)(pp + 8);
            }
            #pragma unroll
            for (int mf = 0; mf < 2; mf++)
                #pragma unroll
                for (int nf = 0; nf < 8; nf++)
                    mma16816(acc[mf][nf], a[mf], b[nf]);
        }

        #pragma unroll
        for (int mf = 0; mf < 2; mf++)
            #pragma unroll
            for (int nf = 0; nf < 8; nf++)
                #pragma unroll
                for (int e2 = 0; e2 < 4; e2++) {
                    int rgl = ibase + warp_m * 32 + mf * 16 + g + ((e2 >> 1) << 3);
                    int cg  = jbase + warp_n * 64 + nf * 8 + q * 2 + (e2 & 1);
                    float ev = (rgl == cg) ? 0.f : exp2f(acc[mf][nf][e2]);
                    rowsum[mf][e2 >> 1] += ev;
                }
    }

    #pragma unroll
    for (int mf = 0; mf < 2; mf++)
        #pragma unroll
        for (int h = 0; h < 2; h++) {
            float s = rowsum[mf][h];
            s += __shfl_xor_sync(0xffffffffu, s, 1);
            s += __shfl_xor_sync(0xffffffffu, s, 2);
            if (q == 0)
                atomicAdd(&d_S[ibase + warp_m * 32 + mf * 16 + g + h * 8], s);
        }
#endif

    // -------- last-block final reduction --------
    __shared__ double red[8];
    __shared__ int lastflag;
    __threadfence();
    __syncthreads();
    if (tid == 0) {
        unsigned v = atomicAdd(&d_count, 1u);
        lastflag = (v == NBLK - 1);
    }
    __syncthreads();
    if (lastflag) {
        __threadfence();
        double s = 0.0;
        for (int i = tid; i < NROWS; i += 256) s += (double)__logf(d_S[i]);
        for (int i = tid; i < NB;    i += 256) s -= 20.0 * (double)d_pos[i];
        #pragma unroll
        for (int o = 16; o; o >>= 1) s += __shfl_xor_sync(0xffffffffu, s, o);
        if ((tid & 31) == 0) red[tid >> 5] = s;
        __syncthreads();
        if (tid == 0) {
            double t2 = 0.0;
            #pragma unroll
            for (int u = 0; u < 8; u++) t2 += red[u];
            out[0] = (float)(t2 / (double)NROWS);
        }
    }
}

// ------------------------------------------------------------------ launch
extern "C" void kernel_launch(void* const* d_in, const int* in_sizes, int n_in,
                              void* d_out, int out_size) {
    const float* xi = (const float*)d_in[0];
    const float* xj = (const float*)d_in[1];
    float* out = (float*)d_out;

    cudaFuncSetAttribute(sim_kernel,
                         cudaFuncAttributeMaxDynamicSharedMemorySize, SMEM_TOT);

    normalize_kernel<<<NB / 8, 256>>>(xi, xj);
    dim3 grid(NROWS / BM, JSPLIT);
    sim_kernel<<<grid, 256, SMEM_TOT>>>(out);
}